// round 16
// baseline (speedup 1.0000x reference)
#include <cuda_runtime.h>
#include <cuda_fp16.h>

// ============================================================================
// ChebNet R16 = R14 config + scatter fused into layer-1 kernel (phase 0).
// Makes the first heavy prop launch #4 -> lands in ncu's capture window.
// ============================================================================

#define FULLMASK 0xffffffffu

static constexpr int NMAX = 131072;
static constexpr int EMAX = 2000000;
static constexpr int NBMAX = 128;

// ---- static device scratch ----
__device__ int    g_deg[NMAX];
__device__ int    g_cnt[NMAX];
__device__ float  g_dinv[NMAX];
__device__ int    g_rp[NMAX + 1];
__device__ int    g_cursor[NMAX];
__device__ int    g_bsum[NBMAX];
__device__ unsigned int g_barc[8];   // 0-3: layer1 phases, 4: scan, 5: scatter
__device__ int2   g_epack[EMAX];
__device__ float  g_t1[NMAX], g_t2[NMAX], g_t3[NMAX], g_t4[NMAX];
__device__ __half g_X0[NMAX * 64];
__device__ __half g_X1[NMAX * 64];
__device__ __half g_X2[NMAX * 64];
__device__ __half g_X3[NMAX * 64];
__device__ __half g_X4[NMAX * 64];
__device__ float  g_OUT[NMAX * 64];

// ---- f32x2 packed FMA helpers ----
__device__ __forceinline__ unsigned long long pk2(float x, float y) {
    unsigned long long r;
    asm("mov.b64 %0, {%1, %2};" : "=l"(r) : "f"(x), "f"(y));
    return r;
}
__device__ __forceinline__ void fma2(unsigned long long& d,
                                     unsigned long long a, unsigned long long b) {
    asm("fma.rn.f32x2 %0, %1, %2, %0;" : "+l"(d) : "l"(a), "l"(b));
}
__device__ __forceinline__ float2 upk2(unsigned long long v) {
    float2 f;
    asm("mov.b64 {%0, %1}, %2;" : "=f"(f.x), "=f"(f.y) : "l"(v));
    return f;
}

// ---- software grid barrier (all blocks co-resident) ----
__device__ __forceinline__ void grid_bar(unsigned int* barc, int slot, unsigned nb) {
    __syncthreads();
    if (threadIdx.x == 0) {
        __threadfence();
        atomicAdd(&barc[slot], 1u);
        while (atomicAdd(&barc[slot], 0u) < nb) { }
        __threadfence();
    }
    __syncthreads();
}

// ============================================================================
// Preprocessing
// ============================================================================

__global__ void deg_hist_kernel(const int* __restrict__ ei, int E,
                                int* __restrict__ deg, int* __restrict__ cnt) {
    int e = blockIdx.x * blockDim.x + threadIdx.x;
    if (e < E) {
        atomicAdd(&deg[ei[e]], 1);
        atomicAdd(&cnt[ei[E + e]], 1);
    }
}

__global__ __launch_bounds__(1024) void scan_fused_kernel(
        const int* __restrict__ cnt_in, const int* __restrict__ deg_in,
        int* __restrict__ rp, int* __restrict__ cursor,
        float* __restrict__ dinv, int* __restrict__ bsum,
        int* __restrict__ cnt, int* __restrict__ deg,
        int N, int nb, unsigned int* __restrict__ barc) {
    __shared__ int s[1024];
    int idx = blockIdx.x * 1024 + threadIdx.x;
    int v = (idx < N) ? cnt_in[idx] : 0;
    s[threadIdx.x] = v;
    __syncthreads();
    for (int off = 1; off < 1024; off <<= 1) {
        int t = (threadIdx.x >= off) ? s[threadIdx.x - off] : 0;
        __syncthreads();
        s[threadIdx.x] += t;
        __syncthreads();
    }
    int rpl = s[threadIdx.x] - v;
    if (idx < N) {
        int d = deg_in[idx];
        dinv[idx] = (d > 0) ? rsqrtf((float)d) : 0.0f;
    }
    if (threadIdx.x == 1023) bsum[blockIdx.x] = s[1023];

    grid_bar(barc, 4, gridDim.x);

    __shared__ int sb[NBMAX];
    if (threadIdx.x < NBMAX)
        sb[threadIdx.x] = (threadIdx.x < nb) ? bsum[threadIdx.x] : 0;
    __syncthreads();
    for (int off = 1; off < NBMAX; off <<= 1) {
        int t = (threadIdx.x < NBMAX && threadIdx.x >= off) ? sb[threadIdx.x - off] : 0;
        __syncthreads();
        if (threadIdx.x < NBMAX) sb[threadIdx.x] += t;
        __syncthreads();
    }
    int soff = (blockIdx.x == 0) ? 0 : sb[blockIdx.x - 1];
    if (blockIdx.x == (unsigned)(gridDim.x - 1) && threadIdx.x == 0)
        rp[N] = sb[nb - 1];
    if (idx < N) {
        int r = rpl + soff;
        rp[idx] = r;
        cursor[idx] = r;
        cnt[idx] = 0;
        deg[idx] = 0;
    }
    // zero layer1's barrier slots (0-3) and the scatter slot (5)
    if (blockIdx.x == 0 && threadIdx.x < 6 && threadIdx.x != 4)
        barc[threadIdx.x] = 0;
}

// ============================================================================
// Layer 1 fused kernel:
//   phase 0: scatter edges -> epack (grid-stride over E, atomic cursor)
//   phases 1-4: scalar Chebyshev t1..t4 (2 threads/node, pair shfl)
//   tail: combine -> H (fp16)
// ============================================================================

__device__ __forceinline__ float l1_gather2(const float* __restrict__ tin,
                                            const int* __restrict__ rp,
                                            const int2* __restrict__ epack,
                                            int n, int h) {
    float acc = 0.0f;
    int e1 = __ldg(&rp[n + 1]);
    #pragma unroll 4
    for (int e = __ldg(&rp[n]) + h; e < e1; e += 2) {
        int2 md = __ldg(&epack[e]);
        acc += tin[md.x] * __int_as_float(md.y);
    }
    acc += __shfl_xor_sync(FULLMASK, acc, 1);
    return acc;
}

__global__ __launch_bounds__(256, 6) void scatter_layer1_kernel(
        const int* __restrict__ ei, int E,
        const float* __restrict__ dinv, int* __restrict__ cursor,
        int2* __restrict__ epack,
        const float* __restrict__ x,
        float* __restrict__ t1, float* __restrict__ t2,
        float* __restrict__ t3, float* __restrict__ t4,
        const int* __restrict__ rp,
        const float* __restrict__ W1, const float* __restrict__ b1,
        __half* __restrict__ H, int N, unsigned int* __restrict__ barc) {
    const unsigned nb = gridDim.x;
    int gtid = blockIdx.x * blockDim.x + threadIdx.x;
    int nthreads = gridDim.x * blockDim.x;
    if (blockIdx.x == 0 && threadIdx.x == 0) barc[4] = 0;   // clean scan slot

    // phase 0: scatter
    for (int e = gtid; e < E; e += nthreads) {
        int s = ei[e];
        int d = ei[E + e];
        float nm = -(dinv[s] * dinv[d]);
        int pos = atomicAdd(&cursor[d], 1);
        epack[pos] = make_int2(s, __float_as_int(nm));
    }
    grid_bar(barc, 5, nb);

    int n = gtid >> 1;
    int h = gtid & 1;
    bool act = (n < N);
    bool wr = act && (h == 0);

    float a;
    a = act ? l1_gather2(x, rp, epack, n, h) : 0.f;
    if (wr) t1[n] = a;
    grid_bar(barc, 0, nb);
    a = act ? l1_gather2(t1, rp, epack, n, h) : 0.f;
    if (wr) t2[n] = 2.0f * a - x[n];
    grid_bar(barc, 1, nb);
    a = act ? l1_gather2(t2, rp, epack, n, h) : 0.f;
    if (wr) t3[n] = 2.0f * a - t1[n];
    grid_bar(barc, 2, nb);
    a = act ? l1_gather2(t3, rp, epack, n, h) : 0.f;
    if (wr) t4[n] = 2.0f * a - t2[n];
    grid_bar(barc, 3, nb);

    int wid_g = gtid >> 5;
    int l = threadIdx.x & 31;
    int nwarps = nthreads >> 5;
    for (int m = wid_g; m < N; m += nwarps) {
        float v0 = __ldg(&x[m]),  v1 = __ldg(&t1[m]), v2 = __ldg(&t2[m]);
        float v3 = __ldg(&t3[m]), v4 = __ldg(&t4[m]);
        int j = 2 * l;
        float2 o  = *(const float2*)&b1[j];
        float2 w0 = *(const float2*)&W1[0 * 64 + j];
        float2 w1 = *(const float2*)&W1[1 * 64 + j];
        float2 w2 = *(const float2*)&W1[2 * 64 + j];
        float2 w3 = *(const float2*)&W1[3 * 64 + j];
        float2 w4 = *(const float2*)&W1[4 * 64 + j];
        o.x += v0 * w0.x + v1 * w1.x + v2 * w2.x + v3 * w3.x + v4 * w4.x;
        o.y += v0 * w0.y + v1 * w1.y + v2 * w2.y + v3 * w3.y + v4 * w4.y;
        o.x = fmaxf(o.x, 0.0f);
        o.y = fmaxf(o.y, 0.0f);
        ((__half2*)H)[m * 32 + l] = __floats2half2_rn(o.x, o.y);
    }
}

// ============================================================================
// Chebyshev gather prop (fp16 rows, fp32 accumulate), epack-prefetch pipeline.
// ============================================================================

template <bool FIRST>
__global__ __launch_bounds__(256) void prop_cheb_h_kernel(
        const __half* __restrict__ Tin,
        const __half* __restrict__ Tprev,
        __half* __restrict__ Tout,
        const int* __restrict__ rp,
        const int2* __restrict__ epack, int N) {
    const float4* Tin4 = (const float4*)Tin;
    int warp = threadIdx.x >> 5, lane = threadIdx.x & 31;
    int q = lane >> 3;
    int f = lane & 7;
    int wpb = blockDim.x >> 5;
    for (int n = blockIdx.x * wpb + warp; n < N; n += gridDim.x * wpb) {
        int e0 = rp[n], e1 = rp[n + 1];
        float2 a0 = make_float2(0.f, 0.f), a1 = a0, a2 = a0, a3 = a0;
        int e = e0 + q;
        if (e < e1) {
            int2 md = __ldg(&epack[e]);
            e += 4;
            #pragma unroll 2
            while (e < e1) {
                int2 mdn = __ldg(&epack[e]);
                float nm = __int_as_float(md.y);
                float4 v = Tin4[(size_t)md.x * 8 + f];
                float2 f0 = __half22float2(*(const __half2*)&v.x);
                float2 f1 = __half22float2(*(const __half2*)&v.y);
                float2 f2 = __half22float2(*(const __half2*)&v.z);
                float2 f3 = __half22float2(*(const __half2*)&v.w);
                a0.x += nm * f0.x; a0.y += nm * f0.y;
                a1.x += nm * f1.x; a1.y += nm * f1.y;
                a2.x += nm * f2.x; a2.y += nm * f2.y;
                a3.x += nm * f3.x; a3.y += nm * f3.y;
                md = mdn;
                e += 4;
            }
            {
                float nm = __int_as_float(md.y);
                float4 v = Tin4[(size_t)md.x * 8 + f];
                float2 f0 = __half22float2(*(const __half2*)&v.x);
                float2 f1 = __half22float2(*(const __half2*)&v.y);
                float2 f2 = __half22float2(*(const __half2*)&v.z);
                float2 f3 = __half22float2(*(const __half2*)&v.w);
                a0.x += nm * f0.x; a0.y += nm * f0.y;
                a1.x += nm * f1.x; a1.y += nm * f1.y;
                a2.x += nm * f2.x; a2.y += nm * f2.y;
                a3.x += nm * f3.x; a3.y += nm * f3.y;
            }
        }
        #pragma unroll
        for (int off = 8; off <= 16; off <<= 1) {
            a0.x += __shfl_xor_sync(FULLMASK, a0.x, off);
            a0.y += __shfl_xor_sync(FULLMASK, a0.y, off);
            a1.x += __shfl_xor_sync(FULLMASK, a1.x, off);
            a1.y += __shfl_xor_sync(FULLMASK, a1.y, off);
            a2.x += __shfl_xor_sync(FULLMASK, a2.x, off);
            a2.y += __shfl_xor_sync(FULLMASK, a2.y, off);
            a3.x += __shfl_xor_sync(FULLMASK, a3.x, off);
            a3.y += __shfl_xor_sync(FULLMASK, a3.y, off);
        }
        if (q == 0) {
            if (!FIRST) {
                float4 pv = ((const float4*)Tprev)[(size_t)n * 8 + f];
                float2 p0 = __half22float2(*(const __half2*)&pv.x);
                float2 p1 = __half22float2(*(const __half2*)&pv.y);
                float2 p2 = __half22float2(*(const __half2*)&pv.z);
                float2 p3 = __half22float2(*(const __half2*)&pv.w);
                a0.x = 2.f * a0.x - p0.x; a0.y = 2.f * a0.y - p0.y;
                a1.x = 2.f * a1.x - p1.x; a1.y = 2.f * a1.y - p1.y;
                a2.x = 2.f * a2.x - p2.x; a2.y = 2.f * a2.y - p2.y;
                a3.x = 2.f * a3.x - p3.x; a3.y = 2.f * a3.y - p3.y;
            }
            float4 st;
            ((__half2*)&st)[0] = __floats2half2_rn(a0.x, a0.y);
            ((__half2*)&st)[1] = __floats2half2_rn(a1.x, a1.y);
            ((__half2*)&st)[2] = __floats2half2_rn(a2.x, a2.y);
            ((__half2*)&st)[3] = __floats2half2_rn(a3.x, a3.y);
            ((float4*)Tout)[(size_t)n * 8 + f] = st;
        }
    }
}

// ============================================================================
// GEMM pieces (fp16 A staged->fp32 smem; f32x2 inner loop; original weights).
// ============================================================================

static constexpr int GEMMP_SMEM = (256 * 64 + 128 * 32) * 4;   // 81920
static constexpr int GEMMF_SMEM = (64 * 64 + 128 * 32) * 4;    // 32768

__device__ __forceinline__ void stage_a_h(const __half* __restrict__ src,
                                          float4* __restrict__ As4,
                                          int grow, int lm, int lcol, int N) {
    float4 v0, v1, v2, v3;
    if (grow < N) {
        const float4* s4 = (const float4*)(src + (size_t)grow * 64 + lcol);
        float4 r0 = s4[0];
        float4 r1 = s4[1];
        float2 p0 = __half22float2(*(const __half2*)&r0.x);
        float2 p1 = __half22float2(*(const __half2*)&r0.y);
        float2 p2 = __half22float2(*(const __half2*)&r0.z);
        float2 p3 = __half22float2(*(const __half2*)&r0.w);
        float2 p4 = __half22float2(*(const __half2*)&r1.x);
        float2 p5 = __half22float2(*(const __half2*)&r1.y);
        float2 p6 = __half22float2(*(const __half2*)&r1.z);
        float2 p7 = __half22float2(*(const __half2*)&r1.w);
        v0 = make_float4(p0.x, p0.y, p1.x, p1.y);
        v1 = make_float4(p2.x, p2.y, p3.x, p3.y);
        v2 = make_float4(p4.x, p4.y, p5.x, p5.y);
        v3 = make_float4(p6.x, p6.y, p7.x, p7.y);
    } else v0 = v1 = v2 = v3 = make_float4(0.f, 0.f, 0.f, 0.f);
    int ab = lm * 8 + (lcol >> 2);
    As4[ab + 0] = v0; As4[ab + 1] = v1; As4[ab + 2] = v2; As4[ab + 3] = v3;
}

__global__ __launch_bounds__(256) void gemm_partial_kernel(
        const __half* __restrict__ A0, const __half* __restrict__ A1,
        const __half* __restrict__ A2, const __half* __restrict__ A3,
        const float* __restrict__ Wflat, const float* __restrict__ bias,
        float* __restrict__ OUT, int N) {
    extern __shared__ float smem[];
    float*  Bs  = smem;
    float*  As  = smem + 256 * 64;
    float4* Bs4 = (float4*)Bs;
    const ulonglong2* Bs2 = (const ulonglong2*)Bs;
    float4* As4 = (float4*)As;

    for (int i = threadIdx.x; i < 4096; i += 256)
        Bs4[i] = ((const float4*)Wflat)[i];

    const int tid = threadIdx.x;
    const int rg = tid >> 4, cg = tid & 15;
    const int m0 = rg * 8;
    const int blockRow = blockIdx.x * 128;
    const __half* bufs[4] = {A0, A1, A2, A3};

    unsigned long long accL[8], accH[8];
    #pragma unroll
    for (int r = 0; r < 8; ++r) { accL[r] = 0ull; accH[r] = 0ull; }

    const int lm   = tid >> 1;
    const int lcol = (tid & 1) * 16;
    const int grow = blockRow + lm;

    #pragma unroll
    for (int kc = 0; kc < 8; ++kc) {
        const __half* src = bufs[kc >> 1] + ((kc & 1) << 5);
        __syncthreads();
        stage_a_h(src, As4, grow, lm, lcol, N);
        __syncthreads();

        #pragma unroll
        for (int k4 = 0; k4 < 8; ++k4) {
            int kb = kc * 32 + k4 * 4;
            ulonglong2 b0 = Bs2[(kb + 0) * 16 + cg];
            ulonglong2 b1 = Bs2[(kb + 1) * 16 + cg];
            ulonglong2 b2 = Bs2[(kb + 2) * 16 + cg];
            ulonglong2 b3 = Bs2[(kb + 3) * 16 + cg];
            #pragma unroll
            for (int r = 0; r < 8; ++r) {
                float4 a = As4[(m0 + r) * 8 + k4];
                unsigned long long ax = pk2(a.x, a.x), ay = pk2(a.y, a.y);
                unsigned long long az = pk2(a.z, a.z), aw = pk2(a.w, a.w);
                fma2(accL[r], ax, b0.x); fma2(accH[r], ax, b0.y);
                fma2(accL[r], ay, b1.x); fma2(accH[r], ay, b1.y);
                fma2(accL[r], az, b2.x); fma2(accH[r], az, b2.y);
                fma2(accL[r], aw, b3.x); fma2(accH[r], aw, b3.y);
            }
        }
    }

    float4 bv = *(const float4*)&bias[cg * 4];
    #pragma unroll
    for (int r = 0; r < 8; ++r) {
        int row = blockRow + m0 + r;
        if (row < N) {
            float2 lo = upk2(accL[r]);
            float2 hi = upk2(accH[r]);
            ((float4*)OUT)[(size_t)row * 16 + cg] =
                make_float4(lo.x + bv.x, lo.y + bv.y, hi.x + bv.z, hi.y + bv.w);
        }
    }
}

template <bool FC>
__device__ __forceinline__ void gemm_final_body(
        const __half* __restrict__ A4, const float* __restrict__ W4,
        const float* __restrict__ OUT,
        __half* __restrict__ outH,
        const float* __restrict__ Wfc, const float* __restrict__ bfc,
        float* __restrict__ y, int N) {
    extern __shared__ float smem[];
    float*  Bs  = smem;
    float*  As  = smem + 64 * 64;
    float4* Bs4 = (float4*)Bs;
    const ulonglong2* Bs2 = (const ulonglong2*)Bs;
    float4* As4 = (float4*)As;

    for (int i = threadIdx.x; i < 1024; i += 256)
        Bs4[i] = ((const float4*)W4)[i];

    const int tid = threadIdx.x;
    const int rg = tid >> 4, cg = tid & 15;
    const int m0 = rg * 8;
    const int blockRow = blockIdx.x * 128;

    unsigned long long accL[8], accH[8];
    #pragma unroll
    for (int r = 0; r < 8; ++r) { accL[r] = 0ull; accH[r] = 0ull; }

    const int lm   = tid >> 1;
    const int lcol = (tid & 1) * 16;
    const int grow = blockRow + lm;

    #pragma unroll
    for (int kc = 0; kc < 2; ++kc) {
        const __half* src = A4 + kc * 32;
        __syncthreads();
        stage_a_h(src, As4, grow, lm, lcol, N);
        __syncthreads();

        #pragma unroll
        for (int k4 = 0; k4 < 8; ++k4) {
            int kb = kc * 32 + k4 * 4;
            ulonglong2 b0 = Bs2[(kb + 0) * 16 + cg];
            ulonglong2 b1 = Bs2[(kb + 1) * 16 + cg];
            ulonglong2 b2 = Bs2[(kb + 2) * 16 + cg];
            ulonglong2 b3 = Bs2[(kb + 3) * 16 + cg];
            #pragma unroll
            for (int r = 0; r < 8; ++r) {
                float4 a = As4[(m0 + r) * 8 + k4];
                unsigned long long ax = pk2(a.x, a.x), ay = pk2(a.y, a.y);
                unsigned long long az = pk2(a.z, a.z), aw = pk2(a.w, a.w);
                fma2(accL[r], ax, b0.x); fma2(accH[r], ax, b0.y);
                fma2(accL[r], ay, b1.x); fma2(accH[r], ay, b1.y);
                fma2(accL[r], az, b2.x); fma2(accH[r], az, b2.y);
                fma2(accL[r], aw, b3.x); fma2(accH[r], aw, b3.y);
            }
        }
    }

    float4 wfc;
    float bb = 0.f;
    if (FC) { wfc = *(const float4*)&Wfc[cg * 4]; bb = __ldg(bfc); }

    #pragma unroll
    for (int r = 0; r < 8; ++r) {
        int row = blockRow + m0 + r;
        float2 lo = upk2(accL[r]);
        float2 hi = upk2(accH[r]);
        float4 ov = (row < N) ? ((const float4*)OUT)[(size_t)row * 16 + cg]
                              : make_float4(0.f, 0.f, 0.f, 0.f);
        float4 o = make_float4(fmaxf(lo.x + ov.x, 0.f), fmaxf(lo.y + ov.y, 0.f),
                               fmaxf(hi.x + ov.z, 0.f), fmaxf(hi.y + ov.w, 0.f));
        if (FC) {
            float p = o.x * wfc.x + o.y * wfc.y + o.z * wfc.z + o.w * wfc.w;
            p += __shfl_xor_sync(FULLMASK, p, 1);
            p += __shfl_xor_sync(FULLMASK, p, 2);
            p += __shfl_xor_sync(FULLMASK, p, 4);
            p += __shfl_xor_sync(FULLMASK, p, 8);
            if (cg == 0 && row < N) y[row] = p + bb;
        } else if (row < N) {
            float2 st;
            ((__half2*)&st)[0] = __floats2half2_rn(o.x, o.y);
            ((__half2*)&st)[1] = __floats2half2_rn(o.z, o.w);
            ((float2*)outH)[(size_t)row * 16 + cg] = st;
        }
    }
}

__global__ __launch_bounds__(256) void gemm_final_kernel(
        const __half* __restrict__ A4, const float* __restrict__ W4,
        const float* __restrict__ OUT, __half* __restrict__ outH, int N) {
    gemm_final_body<false>(A4, W4, OUT, outH, nullptr, nullptr, nullptr, N);
}

__global__ __launch_bounds__(256) void gemm_final_fc_kernel(
        const __half* __restrict__ A4, const float* __restrict__ W4,
        const float* __restrict__ OUT,
        const float* __restrict__ Wfc, const float* __restrict__ bfc,
        float* __restrict__ y, int N) {
    gemm_final_body<true>(A4, W4, OUT, nullptr, Wfc, bfc, y, N);
}

// ============================================================================
// Host launch
// ============================================================================

extern "C" void kernel_launch(void* const* d_in, const int* in_sizes, int n_in,
                              void* d_out, int out_size) {
    const float* x   = (const float*)d_in[0];
    const int*   ei  = (const int*)d_in[1];
    const float* W1  = (const float*)d_in[2];
    const float* b1  = (const float*)d_in[3];
    const float* W2  = (const float*)d_in[4];
    const float* b2  = (const float*)d_in[5];
    const float* W3  = (const float*)d_in[6];
    const float* b3  = (const float*)d_in[7];
    const float* Wfc = (const float*)d_in[8];
    const float* bfc = (const float*)d_in[9];
    float* out = (float*)d_out;

    const int N = in_sizes[0];
    const int E = in_sizes[1] / 2;

    int *deg, *cnt, *rp, *cursor, *bsum;
    unsigned int* barc;
    int2* epack;
    float *dinv, *t1, *t2, *t3, *t4, *OUT;
    __half *X0, *X1, *X2, *X3, *X4;
    cudaGetSymbolAddress((void**)&deg,   g_deg);
    cudaGetSymbolAddress((void**)&cnt,   g_cnt);
    cudaGetSymbolAddress((void**)&dinv,  g_dinv);
    cudaGetSymbolAddress((void**)&rp,    g_rp);
    cudaGetSymbolAddress((void**)&cursor,g_cursor);
    cudaGetSymbolAddress((void**)&bsum,  g_bsum);
    cudaGetSymbolAddress((void**)&barc,  g_barc);
    cudaGetSymbolAddress((void**)&epack, g_epack);
    cudaGetSymbolAddress((void**)&t1,    g_t1);
    cudaGetSymbolAddress((void**)&t2,    g_t2);
    cudaGetSymbolAddress((void**)&t3,    g_t3);
    cudaGetSymbolAddress((void**)&t4,    g_t4);
    cudaGetSymbolAddress((void**)&X0,    g_X0);
    cudaGetSymbolAddress((void**)&X1,    g_X1);
    cudaGetSymbolAddress((void**)&X2,    g_X2);
    cudaGetSymbolAddress((void**)&X3,    g_X3);
    cudaGetSymbolAddress((void**)&X4,    g_X4);
    cudaGetSymbolAddress((void**)&OUT,   g_OUT);

    static cudaStream_t s1 = nullptr;
    static cudaEvent_t evP2, evG2, evP3, evG3;
    static int PGRID = 1184;
    static int L1CAP = 888;
    static bool init_done = false;
    if (!init_done) {
        cudaStreamCreateWithFlags(&s1, cudaStreamNonBlocking);
        cudaEventCreateWithFlags(&evP2, cudaEventDisableTiming);
        cudaEventCreateWithFlags(&evG2, cudaEventDisableTiming);
        cudaEventCreateWithFlags(&evP3, cudaEventDisableTiming);
        cudaEventCreateWithFlags(&evG3, cudaEventDisableTiming);
        cudaFuncSetAttribute(gemm_partial_kernel,
                             cudaFuncAttributeMaxDynamicSharedMemorySize, GEMMP_SMEM);
        cudaFuncSetAttribute(gemm_final_kernel,
                             cudaFuncAttributeMaxDynamicSharedMemorySize, GEMMF_SMEM);
        cudaFuncSetAttribute(gemm_final_fc_kernel,
                             cudaFuncAttributeMaxDynamicSharedMemorySize, GEMMF_SMEM);
        int dev = 0, nsm = 148, bpm = 0;
        cudaGetDevice(&dev);
        cudaDeviceGetAttribute(&nsm, cudaDevAttrMultiProcessorCount, dev);
        cudaOccupancyMaxActiveBlocksPerMultiprocessor(
            &bpm, prop_cheb_h_kernel<false>, 256, 0);
        if (bpm < 1) bpm = 1;
        PGRID = nsm * bpm;
        int bpmL1 = 0;
        cudaOccupancyMaxActiveBlocksPerMultiprocessor(
            &bpmL1, scatter_layer1_kernel, 256, 0);
        if (bpmL1 < 1) bpmL1 = 1;
        L1CAP = nsm * bpmL1;
        init_done = true;
    }

    const int EB = (E + 255) / 256;
    const int nb1024 = (N + 1023) / 1024;
    const int GB = (N + 127) / 128;
    int nb_l1 = (2 * N + 255) / 256;
    if (nb_l1 > L1CAP) nb_l1 = L1CAP;   // (not hit at N=100K: 782 <= cap)

    // --- preprocess (2 launches) ---
    deg_hist_kernel<<<EB, 256>>>(ei, E, deg, cnt);
    scan_fused_kernel<<<nb1024, 1024>>>(cnt, deg, rp, cursor, dinv, bsum,
                                        cnt, deg, N, nb1024, barc);

    // --- scatter + layer 1 fused (launch #3) ---
    scatter_layer1_kernel<<<nb_l1, 256>>>(ei, E, dinv, cursor, epack,
                                          x, t1, t2, t3, t4, rp, W1, b1, X0, N, barc);

    // --- layer 2 (first prop = launch #4 -> ncu capture window) ---
    prop_cheb_h_kernel<true ><<<PGRID, 256>>>(X0, nullptr, X1, rp, epack, N);
    prop_cheb_h_kernel<false><<<PGRID, 256>>>(X1, X0,      X2, rp, epack, N);
    prop_cheb_h_kernel<false><<<PGRID, 256>>>(X2, X1,      X3, rp, epack, N);
    cudaEventRecord(evP2, 0);
    cudaStreamWaitEvent(s1, evP2, 0);
    gemm_partial_kernel<<<GB, 256, GEMMP_SMEM, s1>>>(X0, X1, X2, X3, W2, b2, OUT, N);
    cudaEventRecord(evG2, s1);
    prop_cheb_h_kernel<false><<<PGRID, 256>>>(X3, X2, X4, rp, epack, N);
    cudaStreamWaitEvent(0, evG2, 0);
    gemm_final_kernel<<<GB, 256, GEMMF_SMEM>>>(X4, W2 + 4 * 4096, OUT, X0, N);

    // --- layer 3 ---
    prop_cheb_h_kernel<true ><<<PGRID, 256>>>(X0, nullptr, X1, rp, epack, N);
    prop_cheb_h_kernel<false><<<PGRID, 256>>>(X1, X0,      X2, rp, epack, N);
    prop_cheb_h_kernel<false><<<PGRID, 256>>>(X2, X1,      X3, rp, epack, N);
    cudaEventRecord(evP3, 0);
    cudaStreamWaitEvent(s1, evP3, 0);
    gemm_partial_kernel<<<GB, 256, GEMMP_SMEM, s1>>>(X0, X1, X2, X3, W3, b3, OUT, N);
    cudaEventRecord(evG3, s1);
    prop_cheb_h_kernel<false><<<PGRID, 256>>>(X3, X2, X4, rp, epack, N);
    cudaStreamWaitEvent(0, evG3, 0);
    gemm_final_fc_kernel<<<GB, 256, GEMMF_SMEM>>>(X4, W3 + 4 * 4096, OUT, Wfc, bfc, out, N);
}

// round 17
// speedup vs baseline: 1.0323x; 1.0323x over previous
#include <cuda_runtime.h>
#include <cuda_fp16.h>

// ============================================================================
// ChebNet R17 = R14 config (separate scatter) + epack.x pre-scaled by 8
// (float4-row offset) to cut addressing insts in the issue-bound props.
// ============================================================================

#define FULLMASK 0xffffffffu

static constexpr int NMAX = 131072;
static constexpr int EMAX = 2000000;
static constexpr int NBMAX = 128;

// ---- static device scratch ----
__device__ int    g_deg[NMAX];
__device__ int    g_cnt[NMAX];
__device__ float  g_dinv[NMAX];
__device__ int    g_rp[NMAX + 1];
__device__ int    g_cursor[NMAX];
__device__ int    g_bsum[NBMAX];
__device__ unsigned int g_barc[8];   // 0-3: layer1 phases, 4: scan
__device__ int2   g_epack[EMAX];     // (src*8, norm-bits)
__device__ float  g_t1[NMAX], g_t2[NMAX], g_t3[NMAX], g_t4[NMAX];
__device__ __half g_X0[NMAX * 64];
__device__ __half g_X1[NMAX * 64];
__device__ __half g_X2[NMAX * 64];
__device__ __half g_X3[NMAX * 64];
__device__ __half g_X4[NMAX * 64];
__device__ float  g_OUT[NMAX * 64];

// ---- f32x2 packed FMA helpers ----
__device__ __forceinline__ unsigned long long pk2(float x, float y) {
    unsigned long long r;
    asm("mov.b64 %0, {%1, %2};" : "=l"(r) : "f"(x), "f"(y));
    return r;
}
__device__ __forceinline__ void fma2(unsigned long long& d,
                                     unsigned long long a, unsigned long long b) {
    asm("fma.rn.f32x2 %0, %1, %2, %0;" : "+l"(d) : "l"(a), "l"(b));
}
__device__ __forceinline__ float2 upk2(unsigned long long v) {
    float2 f;
    asm("mov.b64 {%0, %1}, %2;" : "=f"(f.x), "=f"(f.y) : "l"(v));
    return f;
}

// ---- software grid barrier (all blocks co-resident) ----
__device__ __forceinline__ void grid_bar(unsigned int* barc, int slot, unsigned nb) {
    __syncthreads();
    if (threadIdx.x == 0) {
        __threadfence();
        atomicAdd(&barc[slot], 1u);
        while (atomicAdd(&barc[slot], 0u) < nb) { }
        __threadfence();
    }
    __syncthreads();
}

// ============================================================================
// Preprocessing
// ============================================================================

__global__ void deg_hist_kernel(const int* __restrict__ ei, int E,
                                int* __restrict__ deg, int* __restrict__ cnt) {
    int e = blockIdx.x * blockDim.x + threadIdx.x;
    if (e < E) {
        atomicAdd(&deg[ei[e]], 1);
        atomicAdd(&cnt[ei[E + e]], 1);
    }
}

__global__ __launch_bounds__(1024) void scan_fused_kernel(
        const int* __restrict__ cnt_in, const int* __restrict__ deg_in,
        int* __restrict__ rp, int* __restrict__ cursor,
        float* __restrict__ dinv, int* __restrict__ bsum,
        int* __restrict__ cnt, int* __restrict__ deg,
        int N, int nb, unsigned int* __restrict__ barc) {
    __shared__ int s[1024];
    int idx = blockIdx.x * 1024 + threadIdx.x;
    int v = (idx < N) ? cnt_in[idx] : 0;
    s[threadIdx.x] = v;
    __syncthreads();
    for (int off = 1; off < 1024; off <<= 1) {
        int t = (threadIdx.x >= off) ? s[threadIdx.x - off] : 0;
        __syncthreads();
        s[threadIdx.x] += t;
        __syncthreads();
    }
    int rpl = s[threadIdx.x] - v;
    if (idx < N) {
        int d = deg_in[idx];
        dinv[idx] = (d > 0) ? rsqrtf((float)d) : 0.0f;
    }
    if (threadIdx.x == 1023) bsum[blockIdx.x] = s[1023];

    grid_bar(barc, 4, gridDim.x);

    __shared__ int sb[NBMAX];
    if (threadIdx.x < NBMAX)
        sb[threadIdx.x] = (threadIdx.x < nb) ? bsum[threadIdx.x] : 0;
    __syncthreads();
    for (int off = 1; off < NBMAX; off <<= 1) {
        int t = (threadIdx.x < NBMAX && threadIdx.x >= off) ? sb[threadIdx.x - off] : 0;
        __syncthreads();
        if (threadIdx.x < NBMAX) sb[threadIdx.x] += t;
        __syncthreads();
    }
    int soff = (blockIdx.x == 0) ? 0 : sb[blockIdx.x - 1];
    if (blockIdx.x == (unsigned)(gridDim.x - 1) && threadIdx.x == 0)
        rp[N] = sb[nb - 1];
    if (idx < N) {
        int r = rpl + soff;
        rp[idx] = r;
        cursor[idx] = r;
        cnt[idx] = 0;
        deg[idx] = 0;
    }
    if (blockIdx.x == 0 && threadIdx.x < 4) barc[threadIdx.x] = 0;
}

// Scatter: epack.x stores src*8 (float4-row offset for fp16 rows).
__global__ void scatter_kernel(const int* __restrict__ ei, int E,
                               const float* __restrict__ dinv,
                               int* __restrict__ cursor,
                               int2* __restrict__ epack) {
    int e = blockIdx.x * blockDim.x + threadIdx.x;
    if (e < E) {
        int s = ei[e];
        int d = ei[E + e];
        float nm = -(dinv[s] * dinv[d]);
        int pos = atomicAdd(&cursor[d], 1);
        epack[pos] = make_int2(s << 3, __float_as_int(nm));
    }
}

// ============================================================================
// Layer 1 fused: 2 threads/node scalar Chebyshev + combine (slots 0-3).
// epack.x is src*8 -> scalar index = ep.x >> 3.
// ============================================================================

__device__ __forceinline__ float l1_gather2(const float* __restrict__ tin,
                                            const int* __restrict__ rp,
                                            const int2* __restrict__ epack,
                                            int n, int h) {
    float acc = 0.0f;
    int e1 = __ldg(&rp[n + 1]);
    #pragma unroll 4
    for (int e = __ldg(&rp[n]) + h; e < e1; e += 2) {
        int2 md = __ldg(&epack[e]);
        acc += tin[md.x >> 3] * __int_as_float(md.y);
    }
    acc += __shfl_xor_sync(FULLMASK, acc, 1);
    return acc;
}

__global__ __launch_bounds__(256, 6) void layer1_fused_kernel(
        const float* __restrict__ x,
        float* __restrict__ t1, float* __restrict__ t2,
        float* __restrict__ t3, float* __restrict__ t4,
        const int* __restrict__ rp, const int2* __restrict__ epack,
        const float* __restrict__ W1, const float* __restrict__ b1,
        __half* __restrict__ H, int N, unsigned int* __restrict__ barc) {
    const unsigned nb = gridDim.x;
    int gtid = blockIdx.x * blockDim.x + threadIdx.x;
    int n = gtid >> 1;
    int h = gtid & 1;
    bool act = (n < N);
    bool wr = act && (h == 0);
    if (blockIdx.x == 0 && threadIdx.x == 0) barc[4] = 0;

    float a;
    a = act ? l1_gather2(x, rp, epack, n, h) : 0.f;
    if (wr) t1[n] = a;
    grid_bar(barc, 0, nb);
    a = act ? l1_gather2(t1, rp, epack, n, h) : 0.f;
    if (wr) t2[n] = 2.0f * a - x[n];
    grid_bar(barc, 1, nb);
    a = act ? l1_gather2(t2, rp, epack, n, h) : 0.f;
    if (wr) t3[n] = 2.0f * a - t1[n];
    grid_bar(barc, 2, nb);
    a = act ? l1_gather2(t3, rp, epack, n, h) : 0.f;
    if (wr) t4[n] = 2.0f * a - t2[n];
    grid_bar(barc, 3, nb);

    int wid_g = gtid >> 5;
    int l = threadIdx.x & 31;
    int nwarps = (gridDim.x * blockDim.x) >> 5;
    for (int m = wid_g; m < N; m += nwarps) {
        float v0 = __ldg(&x[m]),  v1 = __ldg(&t1[m]), v2 = __ldg(&t2[m]);
        float v3 = __ldg(&t3[m]), v4 = __ldg(&t4[m]);
        int j = 2 * l;
        float2 o  = *(const float2*)&b1[j];
        float2 w0 = *(const float2*)&W1[0 * 64 + j];
        float2 w1 = *(const float2*)&W1[1 * 64 + j];
        float2 w2 = *(const float2*)&W1[2 * 64 + j];
        float2 w3 = *(const float2*)&W1[3 * 64 + j];
        float2 w4 = *(const float2*)&W1[4 * 64 + j];
        o.x += v0 * w0.x + v1 * w1.x + v2 * w2.x + v3 * w3.x + v4 * w4.x;
        o.y += v0 * w0.y + v1 * w1.y + v2 * w2.y + v3 * w3.y + v4 * w4.y;
        o.x = fmaxf(o.x, 0.0f);
        o.y = fmaxf(o.y, 0.0f);
        ((__half2*)H)[m * 32 + l] = __floats2half2_rn(o.x, o.y);
    }
}

// ============================================================================
// Chebyshev gather prop (fp16 rows, fp32 accumulate). epack.x = src*8.
// ============================================================================

template <bool FIRST>
__global__ __launch_bounds__(256) void prop_cheb_h_kernel(
        const __half* __restrict__ Tin,
        const __half* __restrict__ Tprev,
        __half* __restrict__ Tout,
        const int* __restrict__ rp,
        const int2* __restrict__ epack, int N) {
    const float4* Tin4 = (const float4*)Tin;
    int warp = threadIdx.x >> 5, lane = threadIdx.x & 31;
    int q = lane >> 3;
    int f = lane & 7;
    int wpb = blockDim.x >> 5;
    for (int n = blockIdx.x * wpb + warp; n < N; n += gridDim.x * wpb) {
        int e0 = rp[n], e1 = rp[n + 1];
        float2 a0 = make_float2(0.f, 0.f), a1 = a0, a2 = a0, a3 = a0;
        int e = e0 + q;
        if (e < e1) {
            int2 md = __ldg(&epack[e]);
            e += 4;
            #pragma unroll 2
            while (e < e1) {
                int2 mdn = __ldg(&epack[e]);
                float nm = __int_as_float(md.y);
                float4 v = __ldg(&Tin4[md.x + f]);
                float2 f0 = __half22float2(*(const __half2*)&v.x);
                float2 f1 = __half22float2(*(const __half2*)&v.y);
                float2 f2 = __half22float2(*(const __half2*)&v.z);
                float2 f3 = __half22float2(*(const __half2*)&v.w);
                a0.x += nm * f0.x; a0.y += nm * f0.y;
                a1.x += nm * f1.x; a1.y += nm * f1.y;
                a2.x += nm * f2.x; a2.y += nm * f2.y;
                a3.x += nm * f3.x; a3.y += nm * f3.y;
                md = mdn;
                e += 4;
            }
            {
                float nm = __int_as_float(md.y);
                float4 v = __ldg(&Tin4[md.x + f]);
                float2 f0 = __half22float2(*(const __half2*)&v.x);
                float2 f1 = __half22float2(*(const __half2*)&v.y);
                float2 f2 = __half22float2(*(const __half2*)&v.z);
                float2 f3 = __half22float2(*(const __half2*)&v.w);
                a0.x += nm * f0.x; a0.y += nm * f0.y;
                a1.x += nm * f1.x; a1.y += nm * f1.y;
                a2.x += nm * f2.x; a2.y += nm * f2.y;
                a3.x += nm * f3.x; a3.y += nm * f3.y;
            }
        }
        #pragma unroll
        for (int off = 8; off <= 16; off <<= 1) {
            a0.x += __shfl_xor_sync(FULLMASK, a0.x, off);
            a0.y += __shfl_xor_sync(FULLMASK, a0.y, off);
            a1.x += __shfl_xor_sync(FULLMASK, a1.x, off);
            a1.y += __shfl_xor_sync(FULLMASK, a1.y, off);
            a2.x += __shfl_xor_sync(FULLMASK, a2.x, off);
            a2.y += __shfl_xor_sync(FULLMASK, a2.y, off);
            a3.x += __shfl_xor_sync(FULLMASK, a3.x, off);
            a3.y += __shfl_xor_sync(FULLMASK, a3.y, off);
        }
        if (q == 0) {
            if (!FIRST) {
                float4 pv = ((const float4*)Tprev)[(size_t)n * 8 + f];
                float2 p0 = __half22float2(*(const __half2*)&pv.x);
                float2 p1 = __half22float2(*(const __half2*)&pv.y);
                float2 p2 = __half22float2(*(const __half2*)&pv.z);
                float2 p3 = __half22float2(*(const __half2*)&pv.w);
                a0.x = 2.f * a0.x - p0.x; a0.y = 2.f * a0.y - p0.y;
                a1.x = 2.f * a1.x - p1.x; a1.y = 2.f * a1.y - p1.y;
                a2.x = 2.f * a2.x - p2.x; a2.y = 2.f * a2.y - p2.y;
                a3.x = 2.f * a3.x - p3.x; a3.y = 2.f * a3.y - p3.y;
            }
            float4 st;
            ((__half2*)&st)[0] = __floats2half2_rn(a0.x, a0.y);
            ((__half2*)&st)[1] = __floats2half2_rn(a1.x, a1.y);
            ((__half2*)&st)[2] = __floats2half2_rn(a2.x, a2.y);
            ((__half2*)&st)[3] = __floats2half2_rn(a3.x, a3.y);
            ((float4*)Tout)[(size_t)n * 8 + f] = st;
        }
    }
}

// ============================================================================
// GEMM pieces (fp16 A staged->fp32 smem; f32x2 inner loop; original weights).
// ============================================================================

static constexpr int GEMMP_SMEM = (256 * 64 + 128 * 32) * 4;   // 81920
static constexpr int GEMMF_SMEM = (64 * 64 + 128 * 32) * 4;    // 32768

__device__ __forceinline__ void stage_a_h(const __half* __restrict__ src,
                                          float4* __restrict__ As4,
                                          int grow, int lm, int lcol, int N) {
    float4 v0, v1, v2, v3;
    if (grow < N) {
        const float4* s4 = (const float4*)(src + (size_t)grow * 64 + lcol);
        float4 r0 = s4[0];
        float4 r1 = s4[1];
        float2 p0 = __half22float2(*(const __half2*)&r0.x);
        float2 p1 = __half22float2(*(const __half2*)&r0.y);
        float2 p2 = __half22float2(*(const __half2*)&r0.z);
        float2 p3 = __half22float2(*(const __half2*)&r0.w);
        float2 p4 = __half22float2(*(const __half2*)&r1.x);
        float2 p5 = __half22float2(*(const __half2*)&r1.y);
        float2 p6 = __half22float2(*(const __half2*)&r1.z);
        float2 p7 = __half22float2(*(const __half2*)&r1.w);
        v0 = make_float4(p0.x, p0.y, p1.x, p1.y);
        v1 = make_float4(p2.x, p2.y, p3.x, p3.y);
        v2 = make_float4(p4.x, p4.y, p5.x, p5.y);
        v3 = make_float4(p6.x, p6.y, p7.x, p7.y);
    } else v0 = v1 = v2 = v3 = make_float4(0.f, 0.f, 0.f, 0.f);
    int ab = lm * 8 + (lcol >> 2);
    As4[ab + 0] = v0; As4[ab + 1] = v1; As4[ab + 2] = v2; As4[ab + 3] = v3;
}

__global__ __launch_bounds__(256) void gemm_partial_kernel(
        const __half* __restrict__ A0, const __half* __restrict__ A1,
        const __half* __restrict__ A2, const __half* __restrict__ A3,
        const float* __restrict__ Wflat, const float* __restrict__ bias,
        float* __restrict__ OUT, int N) {
    extern __shared__ float smem[];
    float*  Bs  = smem;
    float*  As  = smem + 256 * 64;
    float4* Bs4 = (float4*)Bs;
    const ulonglong2* Bs2 = (const ulonglong2*)Bs;
    float4* As4 = (float4*)As;

    for (int i = threadIdx.x; i < 4096; i += 256)
        Bs4[i] = ((const float4*)Wflat)[i];

    const int tid = threadIdx.x;
    const int rg = tid >> 4, cg = tid & 15;
    const int m0 = rg * 8;
    const int blockRow = blockIdx.x * 128;
    const __half* bufs[4] = {A0, A1, A2, A3};

    unsigned long long accL[8], accH[8];
    #pragma unroll
    for (int r = 0; r < 8; ++r) { accL[r] = 0ull; accH[r] = 0ull; }

    const int lm   = tid >> 1;
    const int lcol = (tid & 1) * 16;
    const int grow = blockRow + lm;

    #pragma unroll
    for (int kc = 0; kc < 8; ++kc) {
        const __half* src = bufs[kc >> 1] + ((kc & 1) << 5);
        __syncthreads();
        stage_a_h(src, As4, grow, lm, lcol, N);
        __syncthreads();

        #pragma unroll
        for (int k4 = 0; k4 < 8; ++k4) {
            int kb = kc * 32 + k4 * 4;
            ulonglong2 b0 = Bs2[(kb + 0) * 16 + cg];
            ulonglong2 b1 = Bs2[(kb + 1) * 16 + cg];
            ulonglong2 b2 = Bs2[(kb + 2) * 16 + cg];
            ulonglong2 b3 = Bs2[(kb + 3) * 16 + cg];
            #pragma unroll
            for (int r = 0; r < 8; ++r) {
                float4 a = As4[(m0 + r) * 8 + k4];
                unsigned long long ax = pk2(a.x, a.x), ay = pk2(a.y, a.y);
                unsigned long long az = pk2(a.z, a.z), aw = pk2(a.w, a.w);
                fma2(accL[r], ax, b0.x); fma2(accH[r], ax, b0.y);
                fma2(accL[r], ay, b1.x); fma2(accH[r], ay, b1.y);
                fma2(accL[r], az, b2.x); fma2(accH[r], az, b2.y);
                fma2(accL[r], aw, b3.x); fma2(accH[r], aw, b3.y);
            }
        }
    }

    float4 bv = *(const float4*)&bias[cg * 4];
    #pragma unroll
    for (int r = 0; r < 8; ++r) {
        int row = blockRow + m0 + r;
        if (row < N) {
            float2 lo = upk2(accL[r]);
            float2 hi = upk2(accH[r]);
            ((float4*)OUT)[(size_t)row * 16 + cg] =
                make_float4(lo.x + bv.x, lo.y + bv.y, hi.x + bv.z, hi.y + bv.w);
        }
    }
}

template <bool FC>
__device__ __forceinline__ void gemm_final_body(
        const __half* __restrict__ A4, const float* __restrict__ W4,
        const float* __restrict__ OUT,
        __half* __restrict__ outH,
        const float* __restrict__ Wfc, const float* __restrict__ bfc,
        float* __restrict__ y, int N) {
    extern __shared__ float smem[];
    float*  Bs  = smem;
    float*  As  = smem + 64 * 64;
    float4* Bs4 = (float4*)Bs;
    const ulonglong2* Bs2 = (const ulonglong2*)Bs;
    float4* As4 = (float4*)As;

    for (int i = threadIdx.x; i < 1024; i += 256)
        Bs4[i] = ((const float4*)W4)[i];

    const int tid = threadIdx.x;
    const int rg = tid >> 4, cg = tid & 15;
    const int m0 = rg * 8;
    const int blockRow = blockIdx.x * 128;

    unsigned long long accL[8], accH[8];
    #pragma unroll
    for (int r = 0; r < 8; ++r) { accL[r] = 0ull; accH[r] = 0ull; }

    const int lm   = tid >> 1;
    const int lcol = (tid & 1) * 16;
    const int grow = blockRow + lm;

    #pragma unroll
    for (int kc = 0; kc < 2; ++kc) {
        const __half* src = A4 + kc * 32;
        __syncthreads();
        stage_a_h(src, As4, grow, lm, lcol, N);
        __syncthreads();

        #pragma unroll
        for (int k4 = 0; k4 < 8; ++k4) {
            int kb = kc * 32 + k4 * 4;
            ulonglong2 b0 = Bs2[(kb + 0) * 16 + cg];
            ulonglong2 b1 = Bs2[(kb + 1) * 16 + cg];
            ulonglong2 b2 = Bs2[(kb + 2) * 16 + cg];
            ulonglong2 b3 = Bs2[(kb + 3) * 16 + cg];
            #pragma unroll
            for (int r = 0; r < 8; ++r) {
                float4 a = As4[(m0 + r) * 8 + k4];
                unsigned long long ax = pk2(a.x, a.x), ay = pk2(a.y, a.y);
                unsigned long long az = pk2(a.z, a.z), aw = pk2(a.w, a.w);
                fma2(accL[r], ax, b0.x); fma2(accH[r], ax, b0.y);
                fma2(accL[r], ay, b1.x); fma2(accH[r], ay, b1.y);
                fma2(accL[r], az, b2.x); fma2(accH[r], az, b2.y);
                fma2(accL[r], aw, b3.x); fma2(accH[r], aw, b3.y);
            }
        }
    }

    float4 wfc;
    float bb = 0.f;
    if (FC) { wfc = *(const float4*)&Wfc[cg * 4]; bb = __ldg(bfc); }

    #pragma unroll
    for (int r = 0; r < 8; ++r) {
        int row = blockRow + m0 + r;
        float2 lo = upk2(accL[r]);
        float2 hi = upk2(accH[r]);
        float4 ov = (row < N) ? ((const float4*)OUT)[(size_t)row * 16 + cg]
                              : make_float4(0.f, 0.f, 0.f, 0.f);
        float4 o = make_float4(fmaxf(lo.x + ov.x, 0.f), fmaxf(lo.y + ov.y, 0.f),
                               fmaxf(hi.x + ov.z, 0.f), fmaxf(hi.y + ov.w, 0.f));
        if (FC) {
            float p = o.x * wfc.x + o.y * wfc.y + o.z * wfc.z + o.w * wfc.w;
            p += __shfl_xor_sync(FULLMASK, p, 1);
            p += __shfl_xor_sync(FULLMASK, p, 2);
            p += __shfl_xor_sync(FULLMASK, p, 4);
            p += __shfl_xor_sync(FULLMASK, p, 8);
            if (cg == 0 && row < N) y[row] = p + bb;
        } else if (row < N) {
            float2 st;
            ((__half2*)&st)[0] = __floats2half2_rn(o.x, o.y);
            ((__half2*)&st)[1] = __floats2half2_rn(o.z, o.w);
            ((float2*)outH)[(size_t)row * 16 + cg] = st;
        }
    }
}

__global__ __launch_bounds__(256) void gemm_final_kernel(
        const __half* __restrict__ A4, const float* __restrict__ W4,
        const float* __restrict__ OUT, __half* __restrict__ outH, int N) {
    gemm_final_body<false>(A4, W4, OUT, outH, nullptr, nullptr, nullptr, N);
}

__global__ __launch_bounds__(256) void gemm_final_fc_kernel(
        const __half* __restrict__ A4, const float* __restrict__ W4,
        const float* __restrict__ OUT,
        const float* __restrict__ Wfc, const float* __restrict__ bfc,
        float* __restrict__ y, int N) {
    gemm_final_body<true>(A4, W4, OUT, nullptr, Wfc, bfc, y, N);
}

// ============================================================================
// Host launch
// ============================================================================

extern "C" void kernel_launch(void* const* d_in, const int* in_sizes, int n_in,
                              void* d_out, int out_size) {
    const float* x   = (const float*)d_in[0];
    const int*   ei  = (const int*)d_in[1];
    const float* W1  = (const float*)d_in[2];
    const float* b1  = (const float*)d_in[3];
    const float* W2  = (const float*)d_in[4];
    const float* b2  = (const float*)d_in[5];
    const float* W3  = (const float*)d_in[6];
    const float* b3  = (const float*)d_in[7];
    const float* Wfc = (const float*)d_in[8];
    const float* bfc = (const float*)d_in[9];
    float* out = (float*)d_out;

    const int N = in_sizes[0];
    const int E = in_sizes[1] / 2;

    int *deg, *cnt, *rp, *cursor, *bsum;
    unsigned int* barc;
    int2* epack;
    float *dinv, *t1, *t2, *t3, *t4, *OUT;
    __half *X0, *X1, *X2, *X3, *X4;
    cudaGetSymbolAddress((void**)&deg,   g_deg);
    cudaGetSymbolAddress((void**)&cnt,   g_cnt);
    cudaGetSymbolAddress((void**)&dinv,  g_dinv);
    cudaGetSymbolAddress((void**)&rp,    g_rp);
    cudaGetSymbolAddress((void**)&cursor,g_cursor);
    cudaGetSymbolAddress((void**)&bsum,  g_bsum);
    cudaGetSymbolAddress((void**)&barc,  g_barc);
    cudaGetSymbolAddress((void**)&epack, g_epack);
    cudaGetSymbolAddress((void**)&t1,    g_t1);
    cudaGetSymbolAddress((void**)&t2,    g_t2);
    cudaGetSymbolAddress((void**)&t3,    g_t3);
    cudaGetSymbolAddress((void**)&t4,    g_t4);
    cudaGetSymbolAddress((void**)&X0,    g_X0);
    cudaGetSymbolAddress((void**)&X1,    g_X1);
    cudaGetSymbolAddress((void**)&X2,    g_X2);
    cudaGetSymbolAddress((void**)&X3,    g_X3);
    cudaGetSymbolAddress((void**)&X4,    g_X4);
    cudaGetSymbolAddress((void**)&OUT,   g_OUT);

    static cudaStream_t s1 = nullptr;
    static cudaEvent_t evP2, evG2, evP3, evG3;
    static int PGRID = 1184;
    static int L1CAP = 888;
    static bool init_done = false;
    if (!init_done) {
        cudaStreamCreateWithFlags(&s1, cudaStreamNonBlocking);
        cudaEventCreateWithFlags(&evP2, cudaEventDisableTiming);
        cudaEventCreateWithFlags(&evG2, cudaEventDisableTiming);
        cudaEventCreateWithFlags(&evP3, cudaEventDisableTiming);
        cudaEventCreateWithFlags(&evG3, cudaEventDisableTiming);
        cudaFuncSetAttribute(gemm_partial_kernel,
                             cudaFuncAttributeMaxDynamicSharedMemorySize, GEMMP_SMEM);
        cudaFuncSetAttribute(gemm_final_kernel,
                             cudaFuncAttributeMaxDynamicSharedMemorySize, GEMMF_SMEM);
        cudaFuncSetAttribute(gemm_final_fc_kernel,
                             cudaFuncAttributeMaxDynamicSharedMemorySize, GEMMF_SMEM);
        int dev = 0, nsm = 148, bpm = 0;
        cudaGetDevice(&dev);
        cudaDeviceGetAttribute(&nsm, cudaDevAttrMultiProcessorCount, dev);
        cudaOccupancyMaxActiveBlocksPerMultiprocessor(
            &bpm, prop_cheb_h_kernel<false>, 256, 0);
        if (bpm < 1) bpm = 1;
        PGRID = nsm * bpm;
        int bpmL1 = 0;
        cudaOccupancyMaxActiveBlocksPerMultiprocessor(
            &bpmL1, layer1_fused_kernel, 256, 0);
        if (bpmL1 < 1) bpmL1 = 1;
        L1CAP = nsm * bpmL1;
        init_done = true;
    }

    const int EB = (E + 255) / 256;
    const int nb1024 = (N + 1023) / 1024;
    const int GB = (N + 127) / 128;
    int nb_l1 = (2 * N + 255) / 256;
    if (nb_l1 > L1CAP) nb_l1 = L1CAP;

    // --- preprocess (3 launches) ---
    deg_hist_kernel<<<EB, 256>>>(ei, E, deg, cnt);
    scan_fused_kernel<<<nb1024, 1024>>>(cnt, deg, rp, cursor, dinv, bsum,
                                        cnt, deg, N, nb1024, barc);
    scatter_kernel<<<EB, 256>>>(ei, E, dinv, cursor, epack);

    // --- layer 1 ---
    layer1_fused_kernel<<<nb_l1, 256>>>(x, t1, t2, t3, t4, rp, epack, W1, b1, X0, N, barc);

    // --- layer 2 ---
    prop_cheb_h_kernel<true ><<<PGRID, 256>>>(X0, nullptr, X1, rp, epack, N);
    prop_cheb_h_kernel<false><<<PGRID, 256>>>(X1, X0,      X2, rp, epack, N);
    prop_cheb_h_kernel<false><<<PGRID, 256>>>(X2, X1,      X3, rp, epack, N);
    cudaEventRecord(evP2, 0);
    cudaStreamWaitEvent(s1, evP2, 0);
    gemm_partial_kernel<<<GB, 256, GEMMP_SMEM, s1>>>(X0, X1, X2, X3, W2, b2, OUT, N);
    cudaEventRecord(evG2, s1);
    prop_cheb_h_kernel<false><<<PGRID, 256>>>(X3, X2, X4, rp, epack, N);
    cudaStreamWaitEvent(0, evG2, 0);
    gemm_final_kernel<<<GB, 256, GEMMF_SMEM>>>(X4, W2 + 4 * 4096, OUT, X0, N);

    // --- layer 3 ---
    prop_cheb_h_kernel<true ><<<PGRID, 256>>>(X0, nullptr, X1, rp, epack, N);
    prop_cheb_h_kernel<false><<<PGRID, 256>>>(X1, X0,      X2, rp, epack, N);
    prop_cheb_h_kernel<false><<<PGRID, 256>>>(X2, X1,      X3, rp, epack, N);
    cudaEventRecord(evP3, 0);
    cudaStreamWaitEvent(s1, evP3, 0);
    gemm_partial_kernel<<<GB, 256, GEMMP_SMEM, s1>>>(X0, X1, X2, X3, W3, b3, OUT, N);
    cudaEventRecord(evG3, s1);
    prop_cheb_h_kernel<false><<<PGRID, 256>>>(X3, X2, X4, rp, epack, N);
    cudaStreamWaitEvent(0, evG3, 0);
    gemm_final_fc_kernel<<<GB, 256, GEMMF_SMEM>>>(X4, W3 + 4 * 4096, OUT, Wfc, bfc, out, N);
}